// round 10
// baseline (speedup 1.0000x reference)
#include <cuda_runtime.h>
#include <cuda_bf16.h>
#include <stdint.h>

#define B_  256
#define K_  500
#define KH  250                   // j's per half-block
#define H_  152
#define W_  272
#define HW_ (H_ * W_)
#define ID_MAX 20000
#define HASH_SIZE 1024            // 4KB, load factor 0.49
#define NTHREADS 512
#define NBLOCKS  (B_ * 2)         // 2 blocks per batch
#define ID_MASK  ((1 << 18) - 1)
#define FXP_SCALE 1048576.0f      // 2^20

__device__ unsigned long long g_num_acc  = 0ULL;
__device__ unsigned long long g_mask_acc = 0ULL;
__device__ unsigned           g_count    = 0;

__device__ __forceinline__ unsigned hash_id(int id) {
    return ((unsigned)id * 2654435761u) & (HASH_SIZE - 1);
}

__global__ __launch_bounds__(NTHREADS) void fwd_loss_fused(
    const float* __restrict__ flow,   // [B,2,H,W]
    const float* __restrict__ mask,   // [B,K]
    const int*   __restrict__ index,  // [B,K]
    const int*   __restrict__ ids,    // [B,K]
    const int*   __restrict__ index2, // [B,K]
    const int*   __restrict__ ids2,   // [B,K]
    float*       __restrict__ out)
{
    __shared__ int    hpack[HASH_SIZE];       // (k<<18)|id ; 0 = empty (4KB)
    __shared__ float  s_mask[K_];
    __shared__ int    s_index[K_];
    __shared__ float  red_num[NTHREADS / 32];
    __shared__ float  red_msk[NTHREADS / 32];

    const int tid  = threadIdx.x;
    const int b    = blockIdx.x >> 1;         // batch element
    const int half = blockIdx.x & 1;          // which 250 j's this block probes

    // ---- Issue all coalesced scalar loads first ----
    int   id = 0, id2 = 0, i2 = 0, p = 0;
    float m = 0.0f;
    if (tid < K_) {                            // full build side
        const int g = b * K_ + tid;
        id = __ldg(&ids[g]);
        m  = __ldg(&mask[g]);
        p  = __ldg(&index[g]);
    }
    if (tid < KH) {                            // this block's probe half
        const int g2 = b * K_ + half * KH + tid;
        id2 = __ldg(&ids2[g2]);
        i2  = __ldg(&index2[g2]);
    }

    // Zero the hash (cheap: 4KB) — overlaps with the loads above
    #pragma unroll
    for (int i = tid; i < HASH_SIZE; i += NTHREADS) hpack[i] = 0;
    __syncthreads();

    // ---- Build hash + stage mask/index ----
    if (tid < K_) {
        s_mask[tid]  = m;
        s_index[tid] = p;
        int packed = (tid << 18) | id;         // id in 1..20000, nonzero, unique
        unsigned slot = hash_id(id);
        while (atomicCAS(&hpack[slot], 0, packed) != 0)
            slot = (slot + 1) & (HASH_SIZE - 1);
    }
    __syncthreads();

    // ---- Join + deferred gather (this half's 250 j's) ----
    float lnum  = 0.0f;
    float lmask = (tid < KH) ? s_mask[half * KH + tid] : 0.0f;   // each j once
    if (tid < KH && (unsigned)(id2 - 1) < (unsigned)ID_MAX) {    // 1..20000 only
        unsigned slot = hash_id(id2);
        int x = -1;
        while (true) {
            int pk = hpack[slot];
            if (pk == 0) break;                                  // absent
            if ((pk & ID_MASK) == id2) { x = pk >> 18; break; }
            slot = (slot + 1) & (HASH_SIZE - 1);
        }
        if (x >= 0) {
            float mx = s_mask[x];
            float px = 0.0f, py = 0.0f;
            if (mx != 0.0f) {
                int pp = s_index[x];
                const float* fb = flow + (size_t)b * 2 * HW_;
                px = __ldg(&fb[pp]) * mx;           // channel 0 gather
                py = __ldg(&fb[HW_ + pp]) * mx;     // channel 1 gather
            }
            float vx = (float)(i2 % W_);
            float vy = (float)i2 / (float)W_;
            lnum = fabsf(px - vx) + fabsf(py - vy);
        }
    }

    // ---- Block reduction ----
    const int lane = tid & 31;
    const int warp = tid >> 5;
    #pragma unroll
    for (int off = 16; off > 0; off >>= 1) {
        lnum  += __shfl_down_sync(0xFFFFFFFFu, lnum,  off);
        lmask += __shfl_down_sync(0xFFFFFFFFu, lmask, off);
    }
    if (lane == 0) { red_num[warp] = lnum; red_msk[warp] = lmask; }
    __syncthreads();

    __shared__ bool s_last;
    if (warp == 0) {
        float n  = (lane < NTHREADS / 32) ? red_num[lane] : 0.0f;
        float mm = (lane < NTHREADS / 32) ? red_msk[lane] : 0.0f;
        #pragma unroll
        for (int off = 8; off > 0; off >>= 1) {
            n  += __shfl_down_sync(0xFFFFFFFFu, n,  off);
            mm += __shfl_down_sync(0xFFFFFFFFu, mm, off);
        }
        if (lane == 0) {
            // Deterministic order-independent accumulation: 64-bit fixed point.
            atomicAdd(&g_num_acc,  (unsigned long long)llrintf(n  * FXP_SCALE));
            atomicAdd(&g_mask_acc, (unsigned long long)llrintf(mm * FXP_SCALE));
            __threadfence();
            unsigned prev = atomicAdd(&g_count, 1u);
            s_last = (prev == NBLOCKS - 1);
        }
    }
    __syncthreads();

    // ---- Last block, thread 0: finalize from 2 scalars ----
    if (s_last && tid == 0) {
        __threadfence();
        unsigned long long un = atomicAdd(&g_num_acc,  0ULL);
        unsigned long long um = atomicAdd(&g_mask_acc, 0ULL);
        float nn = (float)((double)(long long)un / (double)FXP_SCALE);
        float mt = (float)((double)(long long)um / (double)FXP_SCALE);
        out[0] = nn / (2.0f * mt + 0.0001f);
        g_num_acc  = 0ULL;   // reset for next graph replay (deterministic)
        g_mask_acc = 0ULL;
        g_count    = 0;
    }
}

extern "C" void kernel_launch(void* const* d_in, const int* in_sizes, int n_in,
                              void* d_out, int out_size) {
    const float* flow   = (const float*)d_in[0];
    const float* mask   = (const float*)d_in[1];
    const int*   index  = (const int*)  d_in[2];
    const int*   ids    = (const int*)  d_in[3];
    const int*   index2 = (const int*)  d_in[4];
    const int*   ids2   = (const int*)  d_in[5];
    float* out = (float*)d_out;

    fwd_loss_fused<<<NBLOCKS, NTHREADS>>>(flow, mask, index, ids, index2, ids2, out);
}

// round 11
// speedup vs baseline: 1.6815x; 1.6815x over previous
#include <cuda_runtime.h>
#include <cuda_bf16.h>
#include <stdint.h>

#define B_  256
#define K_  500
#define H_  152
#define W_  272
#define HW_ (H_ * W_)
#define ID_MAX 20000
#define TABLE_SIZE 20480          // >= ID_MAX+1, padded
#define NTHREADS 512
#define NBLOCKS  B_
#define FXP_SCALE 1048576.0f      // 2^20

__device__ unsigned long long g_num_acc  = 0ULL;
__device__ unsigned long long g_mask_acc = 0ULL;
__device__ unsigned           g_count    = 0;

__global__ __launch_bounds__(NTHREADS) void fwd_loss_fused(
    const float* __restrict__ flow,   // [B,2,H,W]
    const float* __restrict__ mask,   // [B,K]
    const int*   __restrict__ index,  // [B,K]
    const int*   __restrict__ ids,    // [B,K]
    const int*   __restrict__ index2, // [B,K]
    const int*   __restrict__ ids2,   // [B,K]
    float*       __restrict__ out)
{
    __shared__ uint16_t table[TABLE_SIZE];    // table[id] = k+1 ; 0 = absent (40KB)
    __shared__ float2   sxy[K_];              // eager-gathered flow*mask per k
    __shared__ float    red_num[NTHREADS / 32];
    __shared__ int      red_cnt[NTHREADS / 32];

    const int b   = blockIdx.x;
    const int tid = threadIdx.x;

    // ---- Phase A: issue ALL global loads (scalars + dependent gathers) ----
    int   id = 0, id2 = 0, i2 = 0;
    float m = 0.0f, px = 0.0f, py = 0.0f;
    if (tid < K_) {
        const int g = b * K_ + tid;
        id  = __ldg(&ids[g]);
        m   = __ldg(&mask[g]);
        id2 = __ldg(&ids2[g]);
        i2  = __ldg(&index2[g]);
        int p = __ldg(&index[g]);
        if (m != 0.0f) {                       // eager gather (overlaps table setup)
            const float* fb = flow + (size_t)b * 2 * HW_;
            px = __ldg(&fb[p]) * m;            // channel 0
            py = __ldg(&fb[HW_ + p]) * m;      // channel 1
        }
    }

    // Zero the direct table (in flight alongside the loads above)
    {
        uint4* t4 = reinterpret_cast<uint4*>(table);
        #pragma unroll
        for (int i = tid; i < TABLE_SIZE * 2 / 16; i += NTHREADS)
            t4[i] = make_uint4(0, 0, 0, 0);
    }
    __syncthreads();   // table zeroed

    // ---- Fill table + stage gathered values ----
    if (tid < K_) {
        table[id] = (uint16_t)(tid + 1);       // id in 1..20000, unique
        sxy[tid]  = make_float2(px, py);
    }
    __syncthreads();

    // ---- Probe: pure shared-memory join ----
    float lnum = 0.0f;
    if (tid < K_ && (unsigned)(id2 - 1) < (unsigned)ID_MAX) {   // 1..20000 only
        int x1 = (int)table[id2];
        if (x1 != 0) {
            float2 s  = sxy[x1 - 1];
            float  vx = (float)(i2 % W_);
            float  vy = (float)i2 / (float)W_;
            lnum = fabsf(s.x - vx) + fabsf(s.y - vy);
        }
    }

    // ---- Block reduction: lnum via shuffles, mask sum via ballot+popc ----
    const int lane = tid & 31;
    const int warp = tid >> 5;
    unsigned bal = __ballot_sync(0xFFFFFFFFu, (tid < K_) && (m != 0.0f));
    #pragma unroll
    for (int off = 16; off > 0; off >>= 1)
        lnum += __shfl_down_sync(0xFFFFFFFFu, lnum, off);
    if (lane == 0) { red_num[warp] = lnum; red_cnt[warp] = __popc(bal); }
    __syncthreads();

    __shared__ bool s_last;
    if (warp == 0) {
        float n = (lane < NTHREADS / 32) ? red_num[lane] : 0.0f;
        int   c = (lane < NTHREADS / 32) ? red_cnt[lane] : 0;
        #pragma unroll
        for (int off = 8; off > 0; off >>= 1) {
            n += __shfl_down_sync(0xFFFFFFFFu, n, off);
            c += __shfl_down_sync(0xFFFFFFFFu, c, off);
        }
        if (lane == 0) {
            // Deterministic order-independent accumulation: 64-bit fixed point.
            atomicAdd(&g_num_acc,  (unsigned long long)llrintf(n * FXP_SCALE));
            atomicAdd(&g_mask_acc, (unsigned long long)c);
            __threadfence();
            unsigned prev = atomicAdd(&g_count, 1u);
            s_last = (prev == NBLOCKS - 1);
        }
    }
    __syncthreads();

    // ---- Last block, thread 0: finalize from 2 scalars ----
    if (s_last && tid == 0) {
        __threadfence();
        unsigned long long un = atomicAdd(&g_num_acc,  0ULL);
        unsigned long long um = atomicAdd(&g_mask_acc, 0ULL);
        float nn = (float)((double)(long long)un / (double)FXP_SCALE);
        float mt = (float)um;                  // mask sum is an exact count
        out[0] = nn / (2.0f * mt + 0.0001f);
        g_num_acc  = 0ULL;   // reset for next graph replay (deterministic)
        g_mask_acc = 0ULL;
        g_count    = 0;
    }
}

extern "C" void kernel_launch(void* const* d_in, const int* in_sizes, int n_in,
                              void* d_out, int out_size) {
    const float* flow   = (const float*)d_in[0];
    const float* mask   = (const float*)d_in[1];
    const int*   index  = (const int*)  d_in[2];
    const int*   ids    = (const int*)  d_in[3];
    const int*   index2 = (const int*)  d_in[4];
    const int*   ids2   = (const int*)  d_in[5];
    float* out = (float*)d_out;

    fwd_loss_fused<<<NBLOCKS, NTHREADS>>>(flow, mask, index, ids, index2, ids2, out);
}